// round 14
// baseline (speedup 1.0000x reference)
#include <cuda_runtime.h>
#include <cstdint>

#define N_TOK 131072
#define DIM   64
#define QSTG  8
#define KCB   1024

#define TM       128            // tokens per CTA
#define TKC      256            // codewords per SMEM chunk
#define NCHUNK   (KCB / TKC)    // 4
#define NTHREADS 256

typedef unsigned long long ull;

// dynamic smem layout (floats):
//   sA   [TM][DIM]                    : 8192   (fp32 residual, for update/loss/xq)
//   sA2  64 d-rows x 1024B            : 16384  (row d holds 128 dup-pairs {r[t][d],r[t][d]})
//   sBt  64 d-rows x 1024B            : 16384  (row d holds 128 pairs (B[2p][d],B[2p+1][d]), slot p^(d>>2))
//   sCn  [TKC]                        : 256
#define SA_F    0
#define SA2_F   (TM * DIM)                  // 8192
#define SBT_F   (SA2_F + 64 * 256)          // 24576
#define SCN_F   (SBT_F + 64 * 256)          // 40960
#define SMEM_FLOATS (SCN_F + TKC)           // 41216
#define SMEM_BYTES  (SMEM_FLOATS * 4)       // 164864 B

__device__ double g_loss[QSTG];
__device__ float  g_cnorm[QSTG * KCB];

__device__ __forceinline__ void ffma2(ull& d, ull a, ull b) {
    asm("fma.rn.f32x2 %0, %1, %2, %0;" : "+l"(d) : "l"(a), "l"(b));
}
__device__ __forceinline__ ull dup2(float a) {
    ull r; unsigned u = __float_as_uint(a);
    asm("mov.b64 %0, {%1, %1};" : "=l"(r) : "r"(u));
    return r;
}
__device__ __forceinline__ float2 unpack2(ull v) {
    float2 r;
    asm("mov.b64 {%0, %1}, %2;" : "=f"(r.x), "=f"(r.y) : "l"(v));
    return r;
}

// ---------------------------------------------------------------------------
// prep: codeword squared norms + zero loss accumulators
// ---------------------------------------------------------------------------
__global__ void prep_kernel(const float* __restrict__ cb) {
    int k = blockIdx.x * blockDim.x + threadIdx.x;
    if (k < QSTG * KCB) {
        const float* p = cb + (size_t)k * DIM;
        float s0 = 0.f, s1 = 0.f, s2 = 0.f, s3 = 0.f;
#pragma unroll
        for (int d = 0; d < DIM; d += 4) {
            s0 = __fadd_rn(s0, __fmul_rn(p[d + 0], p[d + 0]));
            s1 = __fadd_rn(s1, __fmul_rn(p[d + 1], p[d + 1]));
            s2 = __fadd_rn(s2, __fmul_rn(p[d + 2], p[d + 2]));
            s3 = __fadd_rn(s3, __fmul_rn(p[d + 3], p[d + 3]));
        }
        g_cnorm[k] = __fadd_rn(__fadd_rn(s0, s1), __fadd_rn(s2, s3));
    }
    if (blockIdx.x == 0 && threadIdx.x < QSTG) g_loss[threadIdx.x] = 0.0;
}

// ---------------------------------------------------------------------------
// fused: all 8 VQ stages for one 128-token tile (R2 structure + dup'd A array)
// ---------------------------------------------------------------------------
__global__ void __launch_bounds__(NTHREADS, 1)
vq_kernel(const float* __restrict__ x, const float* __restrict__ cb,
          float* __restrict__ out) {
    extern __shared__ float sm[];
    float* sA  = sm + SA_F;
    float* sA2 = sm + SA2_F;
    float* sBt = sm + SBT_F;
    float* sCn = sm + SCN_F;
    // reduction overlay (reuses sBt region between chunk phases)
    float* redV = sBt;                        // [TM][16]
    int*   redI = (int*)(sBt + TM * 16);      // [TM][16]
    __shared__ int   finIdx[TM];
    __shared__ float wsum[NTHREADS / 32];

    const int tid  = threadIdx.x;
    const int tokg = tid >> 4;    // 0..15 : 8 tokens each
    const int cwg  = tid & 15;    // 0..15 : 8 codeword-pairs per chunk
    const int n0   = blockIdx.x * TM;

    float* out_xq  = out;
    float* out_idx = out + (size_t)N_TOK * DIM;

    // ---- load token tile once ----
    {
        const float4* gin = (const float4*)(x + (size_t)n0 * DIM);
        float4* sA4 = (float4*)sA;
#pragma unroll
        for (int i = tid; i < TM * DIM / 4; i += NTHREADS) sA4[i] = gin[i];
    }
    __syncthreads();
    // ---- build duplicated-pair A array: sA2[d][t] = {r, r} ----
    {
        const int t = tid >> 1, hd = tid & 1;
        const float* rr = sA + t * DIM + hd * 32;
#pragma unroll
        for (int e = 0; e < 32; ++e) {
            int d0 = hd * 32 + e;
            *(ull*)((char*)sA2 + (size_t)d0 * 1024 + (size_t)t * 8) = dup2(rr[e]);
        }
    }

    for (int q = 0; q < QSTG; ++q) {
        const float* cbq = cb + (size_t)q * KCB * DIM;

        float bestv[8];
        int   besti[8];
#pragma unroll
        for (int ti = 0; ti < 8; ++ti) { bestv[ti] = 3.4e38f; besti[ti] = 0; }

        for (int ch = 0; ch < NCHUNK; ++ch) {
            const int k0 = ch * TKC;
            __syncthreads();   // previous users of sBt / sA2 writers done

            // ---- stage B chunk as transposed pairs, swizzled slot = p ^ (d>>2) ----
            {
                const float4* gb = (const float4*)(cbq + (size_t)k0 * DIM);
#pragma unroll
                for (int it = 0; it < 8; ++it) {
                    int L = it * NTHREADS + tid;       // 0..2047
                    int p  = L >> 4;                   // pair index 0..127
                    int dq = L & 15;                   // d quad 0..15
                    float4 v1 = gb[(2 * p) * 16 + dq];
                    float4 v2 = gb[(2 * p + 1) * 16 + dq];
                    const float* a1 = &v1.x;
                    const float* a2 = &v2.x;
                    int swz = p ^ dq;
#pragma unroll
                    for (int m = 0; m < 4; ++m) {
                        float2* dst = (float2*)((char*)sBt + (size_t)(4 * dq + m) * 1024) + swz;
                        *dst = make_float2(a1[m], a2[m]);
                    }
                }
                sCn[tid] = g_cnorm[q * KCB + k0 + tid];
            }
            __syncthreads();

            // ---- 8 tokens x 8 codeword-pairs register tile (A pairs direct) ----
            ull acc[64];
#pragma unroll
            for (int c = 0; c < 64; ++c) acc[c] = 0ull;

            const char* aBase = (const char*)sA2 + (size_t)(tokg * 8) * 8;
#pragma unroll 4
            for (int d = 0; d < DIM; ++d) {
                const ull* aRow = (const ull*)(aBase + (size_t)d * 1024);
                ull a2r[8];
#pragma unroll
                for (int ti = 0; ti < 8; ++ti) a2r[ti] = aRow[ti];
                const ull* bRow = (const ull*)((char*)sBt + (size_t)d * 1024) + (cwg ^ (d >> 2));
                ull b2r[8];
#pragma unroll
                for (int j = 0; j < 8; ++j) b2r[j] = bRow[16 * j];
#pragma unroll
                for (int ti = 0; ti < 8; ++ti)
#pragma unroll
                    for (int j = 0; j < 8; ++j)
                        ffma2(acc[ti * 8 + j], a2r[ti], b2r[j]);
            }

            // ---- running argmin: val = cnorm - 2*dot (R2-exact pipeline) ----
#pragma unroll
            for (int j = 0; j < 8; ++j) {
                const int kl = 2 * (cwg + 16 * j);
                const float2 cn = *(const float2*)(sCn + kl);
                const int kg = k0 + kl;
#pragma unroll
                for (int ti = 0; ti < 8; ++ti) {
                    float2 p = unpack2(acc[ti * 8 + j]);
                    float v0 = fmaf(-2.0f, p.x, cn.x);
                    float v1 = fmaf(-2.0f, p.y, cn.y);
                    bool l0 = v0 < bestv[ti];
                    bestv[ti] = l0 ? v0 : bestv[ti];
                    besti[ti] = l0 ? kg : besti[ti];
                    bool l1 = v1 < bestv[ti];
                    bestv[ti] = l1 ? v1 : bestv[ti];
                    besti[ti] = l1 ? (kg + 1) : besti[ti];
                }
            }
        }
        __syncthreads();

        // ---- cross-thread argmin (16 partials per token), index tiebreak ----
#pragma unroll
        for (int ti = 0; ti < 8; ++ti) {
            int t = tokg * 8 + ti;
            redV[t * 16 + cwg] = bestv[ti];
            redI[t * 16 + cwg] = besti[ti];
        }
        __syncthreads();
        if (tid < TM) {
            float bv = redV[tid * 16];
            int   bi = redI[tid * 16];
#pragma unroll
            for (int g = 1; g < 16; ++g) {
                float v  = redV[tid * 16 + g];
                int   ii = redI[tid * 16 + g];
                if (v < bv || (v == bv && ii < bi)) { bv = v; bi = ii; }
            }
            finIdx[tid] = bi;
            out_idx[(size_t)(n0 + tid) * QSTG + q] = (float)bi;
        }
        __syncthreads();

        // ---- residual update (sA + sA2) + commitment loss ----
        {
            const int t = tid >> 1, h = tid & 1;
            const int idx = finIdx[t];
            const float4* c4 = (const float4*)(cbq + (size_t)idx * DIM + h * 32);
            float4* r4 = (float4*)(sA + t * DIM + h * 32);
            char* a2row = (char*)sA2 + (size_t)t * 8;
            float ls = 0.f;
#pragma unroll
            for (int m = 0; m < 8; ++m) {
                float4 rv = r4[m], cv = c4[m], nv;
                nv.x = __fsub_rn(rv.x, cv.x);
                nv.y = __fsub_rn(rv.y, cv.y);
                nv.z = __fsub_rn(rv.z, cv.z);
                nv.w = __fsub_rn(rv.w, cv.w);
                r4[m] = nv;
                int d0 = h * 32 + m * 4;
                *(ull*)(a2row + (size_t)(d0 + 0) * 1024) = dup2(nv.x);
                *(ull*)(a2row + (size_t)(d0 + 1) * 1024) = dup2(nv.y);
                *(ull*)(a2row + (size_t)(d0 + 2) * 1024) = dup2(nv.z);
                *(ull*)(a2row + (size_t)(d0 + 3) * 1024) = dup2(nv.w);
                ls = fmaf(nv.x, nv.x, ls);
                ls = fmaf(nv.y, nv.y, ls);
                ls = fmaf(nv.z, nv.z, ls);
                ls = fmaf(nv.w, nv.w, ls);
            }
#pragma unroll
            for (int off = 16; off; off >>= 1)
                ls += __shfl_down_sync(0xffffffff, ls, off);
            if ((tid & 31) == 0) wsum[tid >> 5] = ls;
            __syncthreads();
            if (tid == 0) {
                float tot = 0.f;
#pragma unroll
                for (int w = 0; w < NTHREADS / 32; ++w) tot += wsum[w];
                atomicAdd(&g_loss[q], (double)tot);
            }
        }
        // next stage's top-of-chunk __syncthreads orders sA2 writes vs reads
    }
    __syncthreads();

    // ---- xq = x - final_residual ----
    {
        const float4* x4 = (const float4*)(x + (size_t)n0 * DIM);
        const float4* r4 = (const float4*)sA;
        float4* o4 = (float4*)(out_xq + (size_t)n0 * DIM);
#pragma unroll
        for (int i = tid; i < TM * DIM / 4; i += NTHREADS) {
            float4 xv = x4[i], rv = r4[i], ov;
            ov.x = __fsub_rn(xv.x, rv.x);
            ov.y = __fsub_rn(xv.y, rv.y);
            ov.z = __fsub_rn(xv.z, rv.z);
            ov.w = __fsub_rn(xv.w, rv.w);
            o4[i] = ov;
        }
    }
}

// ---------------------------------------------------------------------------
// losses
// ---------------------------------------------------------------------------
__global__ void loss_kernel(float* __restrict__ out) {
    if (threadIdx.x < QSTG)
        out[(size_t)N_TOK * DIM + (size_t)N_TOK * QSTG + threadIdx.x] =
            (float)(g_loss[threadIdx.x] / (double)((size_t)N_TOK * DIM));
}

extern "C" void kernel_launch(void* const* d_in, const int* in_sizes, int n_in,
                              void* d_out, int out_size) {
    const float* x  = (const float*)d_in[0];
    const float* cb = (const float*)d_in[1];
    if (n_in >= 2 && in_sizes[0] == QSTG * KCB * DIM && in_sizes[1] == N_TOK * DIM) {
        const float* t = x; x = cb; cb = t;
    }
    float* out = (float*)d_out;

    cudaFuncSetAttribute(vq_kernel,
                         cudaFuncAttributeMaxDynamicSharedMemorySize, SMEM_BYTES);

    prep_kernel<<<(QSTG * KCB + 255) / 256, 256>>>(cb);
    vq_kernel<<<N_TOK / TM, NTHREADS, SMEM_BYTES>>>(x, cb, out);
    loss_kernel<<<1, 32>>>(out);
}

// round 15
// speedup vs baseline: 1.1487x; 1.1487x over previous
#include <cuda_runtime.h>
#include <cstdint>

#define N_TOK 131072
#define DIM   64
#define QSTG  8
#define KCB   1024

#define TM       128            // tokens per CTA
#define TKC      256            // codewords per SMEM chunk
#define NCHUNK   (KCB / TKC)    // 4
#define NTHREADS 256

typedef unsigned long long ull;

// dynamic smem layout (floats):
//   sA   [TM][DIM]                 : 8192
//   sBt  64 rows x 1024 B (pairs)  : 16384   (row d holds 128 pairs (B[2k][d],B[2k+1][d]), slot = k ^ (d>>2))
//   sCn  [TKC]                     : 256
#define SA_F    0
#define SBT_F   (TM * DIM)                  // 8192
#define SCN_F   (SBT_F + 64 * 256)          // 8192 + 16384
#define SMEM_FLOATS (SCN_F + TKC)
#define SMEM_BYTES  (SMEM_FLOATS * 4)

__device__ double g_loss[QSTG];
__device__ float  g_cnorm[QSTG * KCB];

__device__ __forceinline__ void ffma2(ull& d, ull a, ull b) {
    asm("fma.rn.f32x2 %0, %1, %2, %0;" : "+l"(d) : "l"(a), "l"(b));
}
__device__ __forceinline__ ull dup2(float a) {
    ull r; unsigned u = __float_as_uint(a);
    asm("mov.b64 %0, {%1, %1};" : "=l"(r) : "r"(u));
    return r;
}
__device__ __forceinline__ float2 unpack2(ull v) {
    float2 r;
    asm("mov.b64 {%0, %1}, %2;" : "=f"(r.x), "=f"(r.y) : "l"(v));
    return r;
}

// ---------------------------------------------------------------------------
// prep: codeword squared norms + zero loss accumulators
// ---------------------------------------------------------------------------
__global__ void prep_kernel(const float* __restrict__ cb) {
    int k = blockIdx.x * blockDim.x + threadIdx.x;
    if (k < QSTG * KCB) {
        const float* p = cb + (size_t)k * DIM;
        float s0 = 0.f, s1 = 0.f, s2 = 0.f, s3 = 0.f;
#pragma unroll
        for (int d = 0; d < DIM; d += 4) {
            s0 = __fadd_rn(s0, __fmul_rn(p[d + 0], p[d + 0]));
            s1 = __fadd_rn(s1, __fmul_rn(p[d + 1], p[d + 1]));
            s2 = __fadd_rn(s2, __fmul_rn(p[d + 2], p[d + 2]));
            s3 = __fadd_rn(s3, __fmul_rn(p[d + 3], p[d + 3]));
        }
        g_cnorm[k] = __fadd_rn(__fadd_rn(s0, s1), __fadd_rn(s2, s3));
    }
    if (blockIdx.x == 0 && threadIdx.x < QSTG) g_loss[threadIdx.x] = 0.0;
}

// ---------------------------------------------------------------------------
// fused: all 8 VQ stages for one 128-token tile (residual stays in SMEM)
// ---------------------------------------------------------------------------
__global__ void __launch_bounds__(NTHREADS, 1)
vq_kernel(const float* __restrict__ x, const float* __restrict__ cb,
          float* __restrict__ out) {
    extern __shared__ float sm[];
    float* sA  = sm + SA_F;
    float* sBt = sm + SBT_F;
    float* sCn = sm + SCN_F;
    // reduction overlay (reuses sBt region between chunk phases)
    float* redV = sBt;                        // [TM][16]
    int*   redI = (int*)(sBt + TM * 16);      // [TM][16]
    __shared__ int   finIdx[TM];
    __shared__ float wsum[NTHREADS / 32];

    const int tid  = threadIdx.x;
    const int tokg = tid >> 4;    // 0..15 : 8 tokens each
    const int cwg  = tid & 15;    // 0..15 : 8 codeword-pairs per chunk
    const int n0   = blockIdx.x * TM;

    float* out_xq  = out;
    float* out_idx = out + (size_t)N_TOK * DIM;

    // ---- load token tile once ----
    {
        const float4* gin = (const float4*)(x + (size_t)n0 * DIM);
        float4* sA4 = (float4*)sA;
#pragma unroll
        for (int i = tid; i < TM * DIM / 4; i += NTHREADS) sA4[i] = gin[i];
    }

    for (int q = 0; q < QSTG; ++q) {
        const float* cbq = cb + (size_t)q * KCB * DIM;

        float bestv[8];
        int   besti[8];
#pragma unroll
        for (int ti = 0; ti < 8; ++ti) { bestv[ti] = 3.4e38f; besti[ti] = 0; }

        for (int ch = 0; ch < NCHUNK; ++ch) {
            const int k0 = ch * TKC;
            __syncthreads();   // previous users of sBt / sA writers done

            // ---- stage B chunk as transposed pairs, swizzled slot = p ^ (d>>2) ----
            {
                const float4* gb = (const float4*)(cbq + (size_t)k0 * DIM);
#pragma unroll
                for (int it = 0; it < 8; ++it) {
                    int L = it * NTHREADS + tid;       // 0..2047
                    int p  = L >> 4;                   // pair index 0..127
                    int dq = L & 15;                   // d quad 0..15
                    float4 v1 = gb[(2 * p) * 16 + dq];
                    float4 v2 = gb[(2 * p + 1) * 16 + dq];
                    const float* a1 = &v1.x;
                    const float* a2 = &v2.x;
                    int swz = p ^ dq;
#pragma unroll
                    for (int m = 0; m < 4; ++m) {
                        float2* dst = (float2*)((char*)sBt + (size_t)(4 * dq + m) * 1024) + swz;
                        *dst = make_float2(a1[m], a2[m]);
                    }
                }
                sCn[tid] = g_cnorm[q * KCB + k0 + tid];
            }
            __syncthreads();

            // ---- 8 tokens x 8 codeword-pairs register tile ----
            ull acc[64];
#pragma unroll
            for (int c = 0; c < 64; ++c) acc[c] = 0ull;

            const float* aTok = sA + tokg * 8 * DIM;
#pragma unroll 4
            for (int d = 0; d < DIM; ++d) {
                ull a2r[8];
#pragma unroll
                for (int ti = 0; ti < 8; ++ti)
                    a2r[ti] = dup2(aTok[ti * DIM + d]);
                const ull* bRow = (const ull*)((char*)sBt + (size_t)d * 1024) + (cwg ^ (d >> 2));
                ull b2r[8];
#pragma unroll
                for (int j = 0; j < 8; ++j) b2r[j] = bRow[16 * j];
#pragma unroll
                for (int ti = 0; ti < 8; ++ti)
#pragma unroll
                    for (int j = 0; j < 8; ++j)
                        ffma2(acc[ti * 8 + j], a2r[ti], b2r[j]);
            }

            // ---- running argmin: val = cnorm - 2*dot  (rnorm is a per-token constant) ----
#pragma unroll
            for (int j = 0; j < 8; ++j) {
                const int kl = 2 * (cwg + 16 * j);
                const float2 cn = *(const float2*)(sCn + kl);
                const int kg = k0 + kl;
#pragma unroll
                for (int ti = 0; ti < 8; ++ti) {
                    float2 p = unpack2(acc[ti * 8 + j]);
                    float v0 = fmaf(-2.0f, p.x, cn.x);
                    float v1 = fmaf(-2.0f, p.y, cn.y);
                    bool l0 = v0 < bestv[ti];
                    bestv[ti] = l0 ? v0 : bestv[ti];
                    besti[ti] = l0 ? kg : besti[ti];
                    bool l1 = v1 < bestv[ti];
                    bestv[ti] = l1 ? v1 : bestv[ti];
                    besti[ti] = l1 ? (kg + 1) : besti[ti];
                }
            }
        }
        __syncthreads();

        // ---- cross-thread argmin (16 partials per token), index tiebreak ----
#pragma unroll
        for (int ti = 0; ti < 8; ++ti) {
            int t = tokg * 8 + ti;
            redV[t * 16 + cwg] = bestv[ti];
            redI[t * 16 + cwg] = besti[ti];
        }
        __syncthreads();
        if (tid < TM) {
            float bv = redV[tid * 16];
            int   bi = redI[tid * 16];
#pragma unroll
            for (int g = 1; g < 16; ++g) {
                float v  = redV[tid * 16 + g];
                int   ii = redI[tid * 16 + g];
                if (v < bv || (v == bv && ii < bi)) { bv = v; bi = ii; }
            }
            finIdx[tid] = bi;
            out_idx[(size_t)(n0 + tid) * QSTG + q] = (float)bi;
        }
        __syncthreads();

        // ---- residual update (in SMEM) + commitment loss ----
        {
            const int t = tid >> 1, h = tid & 1;
            const int idx = finIdx[t];
            const float4* c4 = (const float4*)(cbq + (size_t)idx * DIM + h * 32);
            float4* r4 = (float4*)(sA + t * DIM + h * 32);
            float ls = 0.f;
#pragma unroll
            for (int m = 0; m < 8; ++m) {
                float4 rv = r4[m], cv = c4[m], nv;
                nv.x = __fsub_rn(rv.x, cv.x);
                nv.y = __fsub_rn(rv.y, cv.y);
                nv.z = __fsub_rn(rv.z, cv.z);
                nv.w = __fsub_rn(rv.w, cv.w);
                r4[m] = nv;
                ls = fmaf(nv.x, nv.x, ls);
                ls = fmaf(nv.y, nv.y, ls);
                ls = fmaf(nv.z, nv.z, ls);
                ls = fmaf(nv.w, nv.w, ls);
            }
#pragma unroll
            for (int off = 16; off; off >>= 1)
                ls += __shfl_down_sync(0xffffffff, ls, off);
            if ((tid & 31) == 0) wsum[tid >> 5] = ls;
            __syncthreads();
            if (tid == 0) {
                float tot = 0.f;
#pragma unroll
                for (int w = 0; w < NTHREADS / 32; ++w) tot += wsum[w];
                atomicAdd(&g_loss[q], (double)tot);
            }
        }
    }
    __syncthreads();

    // ---- xq = x - final_residual ----
    {
        const float4* x4 = (const float4*)(x + (size_t)n0 * DIM);
        const float4* r4 = (const float4*)sA;
        float4* o4 = (float4*)(out_xq + (size_t)n0 * DIM);
#pragma unroll
        for (int i = tid; i < TM * DIM / 4; i += NTHREADS) {
            float4 xv = x4[i], rv = r4[i], ov;
            ov.x = __fsub_rn(xv.x, rv.x);
            ov.y = __fsub_rn(xv.y, rv.y);
            ov.z = __fsub_rn(xv.z, rv.z);
            ov.w = __fsub_rn(xv.w, rv.w);
            o4[i] = ov;
        }
    }
}

// ---------------------------------------------------------------------------
// losses
// ---------------------------------------------------------------------------
__global__ void loss_kernel(float* __restrict__ out) {
    if (threadIdx.x < QSTG)
        out[(size_t)N_TOK * DIM + (size_t)N_TOK * QSTG + threadIdx.x] =
            (float)(g_loss[threadIdx.x] / (double)((size_t)N_TOK * DIM));
}

extern "C" void kernel_launch(void* const* d_in, const int* in_sizes, int n_in,
                              void* d_out, int out_size) {
    const float* x  = (const float*)d_in[0];
    const float* cb = (const float*)d_in[1];
    if (n_in >= 2 && in_sizes[0] == QSTG * KCB * DIM && in_sizes[1] == N_TOK * DIM) {
        const float* t = x; x = cb; cb = t;
    }
    float* out = (float*)d_out;

    cudaFuncSetAttribute(vq_kernel,
                         cudaFuncAttributeMaxDynamicSharedMemorySize, SMEM_BYTES);

    prep_kernel<<<(QSTG * KCB + 255) / 256, 256>>>(cb);
    vq_kernel<<<N_TOK / TM, NTHREADS, SMEM_BYTES>>>(x, cb, out);
    loss_kernel<<<1, 32>>>(out);
}